// round 6
// baseline (speedup 1.0000x reference)
#include <cuda_runtime.h>
#include <math.h>

// NuclearLattice: D=3, W=64 -> box [-32,32]^3, spin in [-0.5,0.5]
// V0=10, VS=2, A_RANGE=2 (exp(-d2/4) = ex2(d2 * -0.25*log2 e)), KC=1.44,
// EPS=1e-6, PAULI_D2=1e-6.

#define TPB  64    // threads per block
#define TILE 128   // atoms per tile (i and j)
#define IPT  2     // i-atoms per thread

__device__ double       g_acc     = 0.0;
__device__ int          g_blocked = 0;
__device__ unsigned int g_done    = 0;

// CMODE: 0 = no Coulomb, 1 = general Coulomb (q from smem), 2 = all-charged (q==1)
template<bool DIAG, int CMODE>
__device__ __forceinline__ void pair_loop(
    const float4* __restrict__ sa,   // {-2x, -2y, -2z, psq}
    const float2* __restrict__ sb,   // {sp, class}
    const float*  __restrict__ sqv,  // q
    const float* xi, const float* yi, const float* zi, const float* psqi,
    const float* tsp, const float* ci, const float* aq,
    int tid, float* acc, float* pmin, int* pcount)
{
    #pragma unroll 8
    for (int jj = 0; jj < TILE; jj++) {
        const float4 a = sa[jj];
        const float2 b = sb[jj];
        float qj = 0.0f;
        if (CMODE == 1) qj = sqv[jj];

        #pragma unroll
        for (int u = 0; u < IPT; u++) {
            // d2 = psq_i + psq_j - 2*dot (reference's formula)
            float t = fmaf(a.z, zi[u], a.w);
            t       = fmaf(a.y, yi[u], t);
            t       = fmaf(a.x, xi[u], t);
            float d2 = t + psqi[u];
            if (CMODE != 0) d2 = fmaxf(d2, 0.0f);   // rsqrt needs d2 >= 0

            // 5-dim Pauli distance via collapsed class scalar c = sp + 2q
            const float dc  = ci[u] - b.y;
            const float d2c = fmaf(dc, dc, d2);

            float g;
            asm("ex2.approx.f32 %0, %1;" : "=f"(g) : "f"(d2 * -0.36067376f));
            const float coef = fmaf(tsp[u], b.x, -10.0f);   // -V0 + VS*ss

            float r = 0.0f, cq = 0.0f;
            if (CMODE != 0) {
                asm("rsqrt.approx.f32 %0, %1;" : "=f"(r) : "f"(d2 + 1e-6f));
                cq = (CMODE == 2) ? aq[u] : aq[u] * qj;
            }

            if (DIAG) {
                if (jj != tid + u * TPB) {   // exclude self pair
                    acc[u] = fmaf(coef, g, acc[u]);
                    if (CMODE != 0) acc[u] = fmaf(cq, r, acc[u]);
                    pcount[u] += (d2c < 1e-6f) ? 1 : 0;
                }
            } else {
                acc[u] = fmaf(coef, g, acc[u]);
                if (CMODE != 0) acc[u] = fmaf(cq, r, acc[u]);
                pmin[u] = fminf(pmin[u], d2c);
            }
        }
    }
}

__global__ __launch_bounds__(TPB) void nl_kernel(
    const float* __restrict__ states, int A, int nblocks, float* __restrict__ out)
{
    // Decode triangular block index k -> (bx <= by)
    const int k = blockIdx.x;
    int by = (int)((sqrtf(8.0f * (float)k + 1.0f) - 1.0f) * 0.5f);
    while ((by + 1) * (by + 2) / 2 <= k) by++;
    while (by * (by + 1) / 2 > k)       by--;
    const int bx = k - by * (by + 1) / 2;
    const bool diag = (bx == by);

    __shared__ float4 sa[TILE];
    __shared__ float2 sb[TILE];
    __shared__ float  sqv[TILE];

    const int tid = threadIdx.x;

    // i-atoms (2 per thread); padding pushed far away with zero spin/charge
    float xi[IPT], yi[IPT], zi[IPT], psqi[IPT], tsp[IPT], ci[IPT], aq[IPT];
    bool allqi = true, anyqi = false;
    #pragma unroll
    for (int u = 0; u < IPT; u++) {
        const int i = bx * TILE + tid + u * TPB;
        float x = 1e18f, y = 1e18f, z = 1e18f, sp = 0.0f, q = 0.0f;
        if (i < A) {
            const float* s = states + (size_t)i * 5;
            x = s[0]; y = s[1]; z = s[2]; sp = s[3]; q = s[4] + 0.5f;
        }
        xi[u] = x; yi[u] = y; zi[u] = z;
        psqi[u] = fmaf(x, x, fmaf(y, y, z * z));
        tsp[u]  = 2.0f * sp;
        ci[u]   = fmaf(2.0f, q, sp);
        aq[u]   = 1.44f * q;
        allqi = allqi && (q == 1.0f);
        anyqi = anyqi || (q != 0.0f);

        // Bounds check once per atom (each atom is in exactly one diagonal block)
        if (diag && i < A) {
            const bool bad = (x  < -32.0f) || (x  > 32.0f) ||
                             (y  < -32.0f) || (y  > 32.0f) ||
                             (z  < -32.0f) || (z  > 32.0f) ||
                             (sp < -0.5f)  || (sp > 0.5f);
            if (bad) atomicOr(&g_blocked, 1);
        }
    }

    // j-tile -> smem (2 entries per thread)
    bool allqj = true, anyqj = false;
    #pragma unroll
    for (int u = 0; u < IPT; u++) {
        const int j = by * TILE + tid + u * TPB;
        float x = -1e18f, y = -1e18f, z = -1e18f, sp = 0.0f, q = 0.0f;
        if (j < A) {
            const float* s = states + (size_t)j * 5;
            x = s[0]; y = s[1]; z = s[2]; sp = s[3]; q = s[4] + 0.5f;
        }
        const float psq = fmaf(x, x, fmaf(y, y, z * z));
        sa[tid + u * TPB]  = make_float4(-2.0f * x, -2.0f * y, -2.0f * z, psq);
        sb[tid + u * TPB]  = make_float2(sp, fmaf(2.0f, q, sp));
        sqv[tid + u * TPB] = q;
        allqj = allqj && (q == 1.0f);
        anyqj = anyqj || (q != 0.0f);
    }

    // Runtime-uniform Coulomb mode. NOTE: __syncthreads_or/and are LOGICAL
    // reductions (0 / non-zero), NOT bitwise -- one call per flag.
    // These barriers also serve as the smem-visibility sync.
    const int anyQi = __syncthreads_or(anyqi ? 1 : 0);
    const int anyQj = __syncthreads_or(anyqj ? 1 : 0);
    const int allQ  = __syncthreads_and((allqi && allqj) ? 1 : 0);
    const bool coul = (anyQi != 0) && (anyQj != 0);
    const int  cmode = coul ? ((allQ != 0) ? 2 : 1) : 0;

    float acc[IPT]    = {0.0f, 0.0f};
    float pmin[IPT]   = {1e30f, 1e30f};
    int   pcount[IPT] = {0, 0};

    if (diag) {
        if      (cmode == 0) pair_loop<true, 0>(sa, sb, sqv, xi, yi, zi, psqi, tsp, ci, aq, tid, acc, pmin, pcount);
        else if (cmode == 1) pair_loop<true, 1>(sa, sb, sqv, xi, yi, zi, psqi, tsp, ci, aq, tid, acc, pmin, pcount);
        else                 pair_loop<true, 2>(sa, sb, sqv, xi, yi, zi, psqi, tsp, ci, aq, tid, acc, pmin, pcount);
    } else {
        if      (cmode == 0) pair_loop<false, 0>(sa, sb, sqv, xi, yi, zi, psqi, tsp, ci, aq, tid, acc, pmin, pcount);
        else if (cmode == 1) pair_loop<false, 1>(sa, sb, sqv, xi, yi, zi, psqi, tsp, ci, aq, tid, acc, pmin, pcount);
        else                 pair_loop<false, 2>(sa, sb, sqv, xi, yi, zi, psqi, tsp, ci, aq, tid, acc, pmin, pcount);
    }

    float accs = acc[0] + acc[1];
    if (diag) accs *= 0.5f;   // diag tiles count both orders

    const bool pauli = diag ? (pcount[0] + pcount[1] > 0)
                            : (fminf(pmin[0], pmin[1]) < 1e-6f);
    if (pauli) atomicOr(&g_blocked, 1);

    // Reduce: fp32 per-thread -> double warp -> block (2 warps) -> one atomic
    double v = (double)accs;
    #pragma unroll
    for (int off = 16; off > 0; off >>= 1)
        v += __shfl_down_sync(0xffffffffu, v, off);

    __shared__ double wsum[TPB / 32];
    const int lane = tid & 31;
    const int warp = tid >> 5;
    if (lane == 0) wsum[warp] = v;
    __syncthreads();

    if (tid == 0) {
        v = wsum[0] + wsum[1];
        atomicAdd(&g_acc, v);
        __threadfence();
        const unsigned t = atomicAdd(&g_done, 1u);
        if (t == (unsigned)nblocks - 1u) {
            // Last block: publish result and reset state for next graph replay
            const double e  = atomicAdd(&g_acc, 0.0);
            const int    bl = atomicOr(&g_blocked, 0);
            out[0] = bl ? INFINITY : (float)e;
            g_acc     = 0.0;
            g_blocked = 0;
            __threadfence();
            g_done = 0;
        }
    }
}

extern "C" void kernel_launch(void* const* d_in, const int* in_sizes, int n_in,
                              void* d_out, int out_size) {
    const float* states = (const float*)d_in[0];
    const int A = in_sizes[0] / 5;

    const int tiles   = (A + TILE - 1) / TILE;
    const int nblocks = tiles * (tiles + 1) / 2;

    nl_kernel<<<nblocks, TPB>>>(states, A, nblocks, (float*)d_out);
}

// round 7
// speedup vs baseline: 1.3000x; 1.3000x over previous
#include <cuda_runtime.h>
#include <math.h>

// NuclearLattice: D=3, W=64 -> box [-32,32]^3, spin in [-0.5,0.5]
// V0=10, VS=2, A_RANGE=2, KC=1.44, EPS=1e-6, PAULI_D2=1e-6.
// gauss = exp(-d2/4) = ex2(-CSCL*d2); d2 = d2n * KINV with d2n = -CSCL*d2.

#define TPB  64
#define TILE 128
#define IPT  2

#define CSCL 0.36067376f     // 0.25 * log2(e)
#define KINV (-2.7725887f)   // -1/CSCL = -4*ln(2)

__device__ double       g_acc     = 0.0;
__device__ int          g_blocked = 0;
__device__ unsigned int g_done    = 0;

// ---- fast path: both tiles uniform in (sp,q); coef/cq/dcc are block constants ----

template<bool COUL, bool PAULI>
__device__ __forceinline__ void fast_off(
    const float4* __restrict__ sa,          // {2C*xj, 2C*yj, 2C*zj, -C*psqj}
    const float* xs, const float* ys, const float* zs, const float* npsq,
    float coef, float cq, float* acc, float* pmax)
{
    #pragma unroll 8
    for (int jj = 0; jj < TILE; jj++) {
        const float4 a = sa[jj];
        #pragma unroll
        for (int u = 0; u < IPT; u++) {
            float t = fmaf(a.z, zs[u], a.w);
            t = fmaf(a.y, ys[u], t);
            t = fmaf(a.x, xs[u], t);
            const float d2n = t + npsq[u];          // = -CSCL * d2
            float g;
            asm("ex2.approx.f32 %0, %1;" : "=f"(g) : "f"(d2n));
            acc[u] = fmaf(coef, g, acc[u]);
            if (COUL) {
                const float v = fmaxf(fmaf(d2n, KINV, 1e-6f), 1e-6f); // max(d2,0)+eps
                float r;
                asm("rsqrt.approx.f32 %0, %1;" : "=f"(r) : "f"(v));
                acc[u] = fmaf(cq, r, acc[u]);
            }
            if (PAULI) pmax[u] = fmaxf(pmax[u], d2n);
        }
    }
}

template<bool COUL>
__device__ __forceinline__ void fast_diag(
    const float4* __restrict__ sa,
    const float* xs, const float* ys, const float* zs, const float* npsq,
    float coef, float cq, float thr, int tid, float* acc, int* pcount)
{
    #pragma unroll 8
    for (int jj = 0; jj < TILE; jj++) {
        const float4 a = sa[jj];
        #pragma unroll
        for (int u = 0; u < IPT; u++) {
            float t = fmaf(a.z, zs[u], a.w);
            t = fmaf(a.y, ys[u], t);
            t = fmaf(a.x, xs[u], t);
            const float d2n = t + npsq[u];
            float g;
            asm("ex2.approx.f32 %0, %1;" : "=f"(g) : "f"(d2n));
            float e = coef * g;
            if (COUL) {
                const float v = fmaxf(fmaf(d2n, KINV, 1e-6f), 1e-6f);
                float r;
                asm("rsqrt.approx.f32 %0, %1;" : "=f"(r) : "f"(v));
                e = fmaf(cq, r, e);
            }
            if (jj != tid + u * TPB) {              // exclude self pair
                acc[u] += e;
                pcount[u] += (d2n > thr) ? 1 : 0;
            }
        }
    }
}

// ---- general fallback: exact per-pair spin/charge (any data) ----

template<bool DIAG>
__device__ __forceinline__ void gen_loop(
    const float4* __restrict__ sa,
    const float2* __restrict__ sb,              // {sp, q}
    const float* xs, const float* ys, const float* zs, const float* npsq,
    const float* spv, const float* qv, int tid,
    float* acc, float* pmin, int* pcount)
{
    #pragma unroll 4
    for (int jj = 0; jj < TILE; jj++) {
        const float4 a = sa[jj];
        const float2 b = sb[jj];
        #pragma unroll
        for (int u = 0; u < IPT; u++) {
            float t = fmaf(a.z, zs[u], a.w);
            t = fmaf(a.y, ys[u], t);
            t = fmaf(a.x, xs[u], t);
            const float d2n = t + npsq[u];
            const float d2  = fmaxf(d2n * KINV, 0.0f);
            const float dsp = spv[u] - b.x;
            const float dq  = qv[u]  - b.y;
            const float d2c = fmaf(dsp, dsp, fmaf(dq, dq, d2));
            float g;
            asm("ex2.approx.f32 %0, %1;" : "=f"(g) : "f"(d2n));
            const float coef = fmaf(2.0f * spv[u], b.x, -10.0f);
            float r;
            asm("rsqrt.approx.f32 %0, %1;" : "=f"(r) : "f"(d2 + 1e-6f));
            const float cq = 1.44f * qv[u] * b.y;
            const float e  = fmaf(coef, g, cq * r);
            if (DIAG) {
                if (jj != tid + u * TPB) { acc[u] += e; pcount[u] += (d2c < 1e-6f) ? 1 : 0; }
            } else {
                acc[u] += e; pmin[u] = fminf(pmin[u], d2c);
            }
        }
    }
}

__global__ __launch_bounds__(TPB) void nl_kernel(
    const float* __restrict__ states, int A, int nblocks, float* __restrict__ out)
{
    // Decode triangular block index k -> (bx <= by)
    const int k = blockIdx.x;
    int by = (int)((sqrtf(8.0f * (float)k + 1.0f) - 1.0f) * 0.5f);
    while ((by + 1) * (by + 2) / 2 <= k) by++;
    while (by * (by + 1) / 2 > k)       by--;
    const int bx = k - by * (by + 1) / 2;
    const bool diag = (bx == by);

    __shared__ float4 sa[TILE];
    __shared__ float2 sb[TILE];
    __shared__ float4 uref;   // {sp_i0, q_i0, sp_j0, q_j0}

    const int tid = threadIdx.x;

    // i-atoms (2 per thread); padding far away with zero spin/charge
    float xs[IPT], ys[IPT], zs[IPT], npsq[IPT], spv[IPT], qv[IPT];
    bool viu[IPT];
    #pragma unroll
    for (int u = 0; u < IPT; u++) {
        const int i = bx * TILE + tid + u * TPB;
        viu[u] = (i < A);
        float x = 1e18f, y = 1e18f, z = 1e18f, sp = 0.0f, q = 0.0f;
        if (viu[u]) {
            const float* s = states + (size_t)i * 5;
            x = s[0]; y = s[1]; z = s[2]; sp = s[3]; q = s[4] + 0.5f;
        }
        xs[u] = x; ys[u] = y; zs[u] = z;
        npsq[u] = -CSCL * fmaf(x, x, fmaf(y, y, z * z));
        spv[u] = sp; qv[u] = q;

        // bounds check once per atom (each atom appears in exactly one diag block)
        if (diag && viu[u]) {
            const bool bad = (x  < -32.0f) || (x  > 32.0f) ||
                             (y  < -32.0f) || (y  > 32.0f) ||
                             (z  < -32.0f) || (z  > 32.0f) ||
                             (sp < -0.5f)  || (sp > 0.5f);
            if (bad) atomicOr(&g_blocked, 1);
        }
    }

    // j-tile -> smem; keep j (sp,q) in regs for the uniformity check
    float jsp[IPT], jq[IPT];
    bool vju[IPT];
    #pragma unroll
    for (int u = 0; u < IPT; u++) {
        const int j = by * TILE + tid + u * TPB;
        vju[u] = (j < A);
        float x = -1e18f, y = -1e18f, z = -1e18f, sp = 0.0f, q = 0.0f;
        if (vju[u]) {
            const float* s = states + (size_t)j * 5;
            x = s[0]; y = s[1]; z = s[2]; sp = s[3]; q = s[4] + 0.5f;
        }
        const float psq = fmaf(x, x, fmaf(y, y, z * z));
        sa[tid + u * TPB] = make_float4(2.0f * CSCL * x, 2.0f * CSCL * y,
                                        2.0f * CSCL * z, -CSCL * psq);
        sb[tid + u * TPB] = make_float2(sp, q);
        jsp[u] = sp; jq[u] = q;
    }
    if (tid == 0) uref = make_float4(spv[0], qv[0], jsp[0], jq[0]);
    __syncthreads();

    // tile-pair uniformity: all valid atoms match the first atom of their tile
    bool myuni = true;
    #pragma unroll
    for (int u = 0; u < IPT; u++) {
        myuni = myuni && (!viu[u] || (spv[u] == uref.x && qv[u] == uref.y));
        myuni = myuni && (!vju[u] || (jsp[u] == uref.z && jq[u]  == uref.w));
    }
    const int unified = __syncthreads_and(myuni ? 1 : 0);

    float acc[IPT]    = {0.0f, 0.0f};
    float pmax[IPT]   = {-1e30f, -1e30f};
    float pmin[IPT]   = {1e30f, 1e30f};
    int   pcount[IPT] = {0, 0};
    bool  pauli = false;

    if (unified) {
        const float coef = fmaf(2.0f * uref.x, uref.z, -10.0f);  // -V0 + VS*sp_i*sp_j
        const float cq   = 1.44f * uref.y * uref.w;              // KC*q_i*q_j
        const float dsp  = uref.x - uref.z;
        const float dq   = uref.y - uref.w;
        const float dcc  = fmaf(dsp, dsp, dq * dq);
        const bool  coul = (cq != 0.0f);
        const bool  pact = (dcc < 1e-6f);                        // pauli possible at all
        const float thr  = -(1e-6f - dcc) * CSCL;                // d2n > thr <=> d2+dcc < 1e-6

        if (diag) {
            if (coul) fast_diag<true >(sa, xs, ys, zs, npsq, coef, cq, thr, tid, acc, pcount);
            else      fast_diag<false>(sa, xs, ys, zs, npsq, coef, cq, thr, tid, acc, pcount);
            pauli = (pcount[0] + pcount[1] > 0);
        } else {
            if      ( coul &&  pact) fast_off<true,  true >(sa, xs, ys, zs, npsq, coef, cq, acc, pmax);
            else if ( coul && !pact) fast_off<true,  false>(sa, xs, ys, zs, npsq, coef, cq, acc, pmax);
            else if (!coul &&  pact) fast_off<false, true >(sa, xs, ys, zs, npsq, coef, cq, acc, pmax);
            else                     fast_off<false, false>(sa, xs, ys, zs, npsq, coef, cq, acc, pmax);
            pauli = pact && (fmaxf(pmax[0], pmax[1]) > thr);
        }
    } else {
        if (diag) {
            gen_loop<true >(sa, sb, xs, ys, zs, npsq, spv, qv, tid, acc, pmin, pcount);
            pauli = (pcount[0] + pcount[1] > 0);
        } else {
            gen_loop<false>(sa, sb, xs, ys, zs, npsq, spv, qv, tid, acc, pmin, pcount);
            pauli = (fminf(pmin[0], pmin[1]) < 1e-6f);
        }
    }

    float accs = acc[0] + acc[1];
    if (diag) accs *= 0.5f;                 // diag tiles counted both orders
    if (pauli) atomicOr(&g_blocked, 1);

    // fp32 per-thread -> double warp -> block (2 warps) -> one atomic
    double v = (double)accs;
    #pragma unroll
    for (int off = 16; off > 0; off >>= 1)
        v += __shfl_down_sync(0xffffffffu, v, off);

    __shared__ double wsum[TPB / 32];
    const int lane = tid & 31;
    const int warp = tid >> 5;
    if (lane == 0) wsum[warp] = v;
    __syncthreads();

    if (tid == 0) {
        v = wsum[0] + wsum[1];
        atomicAdd(&g_acc, v);
        __threadfence();
        const unsigned t = atomicAdd(&g_done, 1u);
        if (t == (unsigned)nblocks - 1u) {
            const double e  = atomicAdd(&g_acc, 0.0);
            const int    bl = atomicOr(&g_blocked, 0);
            out[0] = bl ? INFINITY : (float)e;
            g_acc     = 0.0;
            g_blocked = 0;
            __threadfence();
            g_done = 0;
        }
    }
}

extern "C" void kernel_launch(void* const* d_in, const int* in_sizes, int n_in,
                              void* d_out, int out_size) {
    const float* states = (const float*)d_in[0];
    const int A = in_sizes[0] / 5;

    const int tiles   = (A + TILE - 1) / TILE;
    const int nblocks = tiles * (tiles + 1) / 2;

    nl_kernel<<<nblocks, TPB>>>(states, A, nblocks, (float*)d_out);
}

// round 8
// speedup vs baseline: 1.3270x; 1.0207x over previous
#include <cuda_runtime.h>
#include <math.h>

// NuclearLattice: D=3, W=64 -> box [-32,32]^3, spin in [-0.5,0.5]
// V0=10, VS=2, A_RANGE=2, KC=1.44, EPS=1e-6, PAULI_D2=1e-6.
// gauss = exp(-d2/4) = ex2(d2n) with d2n = -CSCL*d2; d2 = d2n*KINV.

#define TPB  128
#define TILE 128

#define CSCL 0.36067376f     // 0.25 * log2(e)
#define KINV (-2.7725887f)   // -1/CSCL = -4*ln(2)

__device__ double       g_acc     = 0.0;
__device__ int          g_blocked = 0;
__device__ unsigned int g_done    = 0;

// ---- fast path: both tiles uniform in (sp,q); coef/cq/dcc are block constants ----

template<bool COUL, bool PAULI>
__device__ __forceinline__ void fast_off(
    const float4* __restrict__ sa,          // {2C*xj, 2C*yj, 2C*zj, -C*psqj}
    float xi, float yi, float zi, float npsqi,
    float coef, float cq, float& acc, float& pmax)
{
    #pragma unroll 8
    for (int jj = 0; jj < TILE; jj++) {
        const float4 a = sa[jj];
        float t = fmaf(a.z, zi, a.w);
        t = fmaf(a.y, yi, t);
        t = fmaf(a.x, xi, t);
        const float d2n = t + npsqi;            // = -CSCL * d2
        float g;
        asm("ex2.approx.f32 %0, %1;" : "=f"(g) : "f"(d2n));
        acc = fmaf(coef, g, acc);
        if (COUL) {
            const float v = fmaxf(fmaf(d2n, KINV, 1e-6f), 1e-6f);   // max(d2,0)+eps
            float r;
            asm("rsqrt.approx.f32 %0, %1;" : "=f"(r) : "f"(v));
            acc = fmaf(cq, r, acc);
        }
        if (PAULI) pmax = fmaxf(pmax, d2n);
    }
}

template<bool COUL>
__device__ __forceinline__ void fast_diag(
    const float4* __restrict__ sa,
    float xi, float yi, float zi, float npsqi,
    float coef, float cq, float thr, int tid, float& acc, int& pcount)
{
    #pragma unroll 8
    for (int jj = 0; jj < TILE; jj++) {
        const float4 a = sa[jj];
        float t = fmaf(a.z, zi, a.w);
        t = fmaf(a.y, yi, t);
        t = fmaf(a.x, xi, t);
        const float d2n = t + npsqi;
        float g;
        asm("ex2.approx.f32 %0, %1;" : "=f"(g) : "f"(d2n));
        float e = coef * g;
        if (COUL) {
            const float v = fmaxf(fmaf(d2n, KINV, 1e-6f), 1e-6f);
            float r;
            asm("rsqrt.approx.f32 %0, %1;" : "=f"(r) : "f"(v));
            e = fmaf(cq, r, e);
        }
        if (jj != tid) {                        // exclude self pair
            acc += e;
            pcount += (d2n > thr) ? 1 : 0;
        }
    }
}

// ---- general fallback: exact per-pair spin/charge (any data) ----

template<bool DIAG>
__device__ __forceinline__ void gen_loop(
    const float4* __restrict__ sa,
    const float2* __restrict__ sb,              // {sp, q}
    float xi, float yi, float zi, float npsqi,
    float spi, float qi, int tid,
    float& acc, float& pmin, int& pcount)
{
    #pragma unroll 4
    for (int jj = 0; jj < TILE; jj++) {
        const float4 a = sa[jj];
        const float2 b = sb[jj];
        float t = fmaf(a.z, zi, a.w);
        t = fmaf(a.y, yi, t);
        t = fmaf(a.x, xi, t);
        const float d2n = t + npsqi;
        const float d2  = fmaxf(d2n * KINV, 0.0f);
        const float dsp = spi - b.x;
        const float dq  = qi  - b.y;
        const float d2c = fmaf(dsp, dsp, fmaf(dq, dq, d2));
        float g;
        asm("ex2.approx.f32 %0, %1;" : "=f"(g) : "f"(d2n));
        const float coef = fmaf(2.0f * spi, b.x, -10.0f);
        float r;
        asm("rsqrt.approx.f32 %0, %1;" : "=f"(r) : "f"(d2 + 1e-6f));
        const float cq = 1.44f * qi * b.y;
        const float e  = fmaf(coef, g, cq * r);
        if (DIAG) {
            if (jj != tid) { acc += e; pcount += (d2c < 1e-6f) ? 1 : 0; }
        } else {
            acc += e; pmin = fminf(pmin, d2c);
        }
    }
}

__global__ __launch_bounds__(TPB) void nl_kernel(
    const float* __restrict__ states, int A, int nblocks, float* __restrict__ out)
{
    // Decode triangular block index k -> (bx <= by)
    const int k = blockIdx.x;
    int by = (int)((sqrtf(8.0f * (float)k + 1.0f) - 1.0f) * 0.5f);
    while ((by + 1) * (by + 2) / 2 <= k) by++;
    while (by * (by + 1) / 2 > k)       by--;
    const int bx = k - by * (by + 1) / 2;
    const bool diag = (bx == by);

    __shared__ float4 sa[TILE];
    __shared__ float2 sb[TILE];
    __shared__ float4 uref;   // {sp_i0, q_i0, sp_j0, q_j0}

    const int tid = threadIdx.x;

    // i-atom; padding far away with zero spin/charge
    const int i = bx * TILE + tid;
    const bool vi = (i < A);
    float xi = 1e18f, yi = 1e18f, zi = 1e18f, spi = 0.0f, qi = 0.0f;
    if (vi) {
        const float* s = states + (size_t)i * 5;
        xi = s[0]; yi = s[1]; zi = s[2]; spi = s[3]; qi = s[4] + 0.5f;
    }
    const float npsqi = -CSCL * fmaf(xi, xi, fmaf(yi, yi, zi * zi));

    // bounds check once per atom (each atom appears in exactly one diag block)
    if (diag && vi) {
        const bool bad = (xi  < -32.0f) || (xi  > 32.0f) ||
                         (yi  < -32.0f) || (yi  > 32.0f) ||
                         (zi  < -32.0f) || (zi  > 32.0f) ||
                         (spi < -0.5f)  || (spi > 0.5f);
        if (bad) atomicOr(&g_blocked, 1);
    }

    // j-tile -> smem; keep j (sp,q) in regs for the uniformity check
    const int j = by * TILE + tid;
    const bool vj = (j < A);
    float jsp = 0.0f, jq = 0.0f;
    {
        float x = -1e18f, y = -1e18f, z = -1e18f;
        if (vj) {
            const float* s = states + (size_t)j * 5;
            x = s[0]; y = s[1]; z = s[2]; jsp = s[3]; jq = s[4] + 0.5f;
        }
        const float psq = fmaf(x, x, fmaf(y, y, z * z));
        sa[tid] = make_float4(2.0f * CSCL * x, 2.0f * CSCL * y,
                              2.0f * CSCL * z, -CSCL * psq);
        sb[tid] = make_float2(jsp, jq);
    }
    if (tid == 0) uref = make_float4(spi, qi, jsp, jq);
    __syncthreads();

    // tile-pair uniformity: all valid atoms match the first atom of their tile
    bool myuni = (!vi || (spi == uref.x && qi == uref.y)) &&
                 (!vj || (jsp == uref.z && jq == uref.w));
    const int unified = __syncthreads_and(myuni ? 1 : 0);

    float acc    = 0.0f;
    float pmax   = -1e30f;
    float pmin   = 1e30f;
    int   pcount = 0;
    bool  pauli  = false;

    if (unified) {
        const float coef = fmaf(2.0f * uref.x, uref.z, -10.0f);  // -V0 + VS*sp_i*sp_j
        const float cq   = 1.44f * uref.y * uref.w;              // KC*q_i*q_j
        const float dsp  = uref.x - uref.z;
        const float dq   = uref.y - uref.w;
        const float dcc  = fmaf(dsp, dsp, dq * dq);
        const bool  coul = (cq != 0.0f);
        const bool  pact = (dcc < 1e-6f);                        // pauli possible at all
        const float thr  = -(1e-6f - dcc) * CSCL;                // d2n > thr <=> d2+dcc < 1e-6

        if (diag) {
            if (coul) fast_diag<true >(sa, xi, yi, zi, npsqi, coef, cq, thr, tid, acc, pcount);
            else      fast_diag<false>(sa, xi, yi, zi, npsqi, coef, cq, thr, tid, acc, pcount);
            pauli = (pcount > 0);
        } else {
            if      ( coul &&  pact) fast_off<true,  true >(sa, xi, yi, zi, npsqi, coef, cq, acc, pmax);
            else if ( coul && !pact) fast_off<true,  false>(sa, xi, yi, zi, npsqi, coef, cq, acc, pmax);
            else if (!coul &&  pact) fast_off<false, true >(sa, xi, yi, zi, npsqi, coef, cq, acc, pmax);
            else                     fast_off<false, false>(sa, xi, yi, zi, npsqi, coef, cq, acc, pmax);
            pauli = pact && (pmax > thr);
        }
    } else {
        if (diag) {
            gen_loop<true >(sa, sb, xi, yi, zi, npsqi, spi, qi, tid, acc, pmin, pcount);
            pauli = (pcount > 0);
        } else {
            gen_loop<false>(sa, sb, xi, yi, zi, npsqi, spi, qi, tid, acc, pmin, pcount);
            pauli = (pmin < 1e-6f);
        }
    }

    if (diag) acc *= 0.5f;                  // diag tiles counted both orders
    if (pauli) atomicOr(&g_blocked, 1);

    // fp32 per-thread -> double warp -> block (4 warps) -> one atomic
    double v = (double)acc;
    #pragma unroll
    for (int off = 16; off > 0; off >>= 1)
        v += __shfl_down_sync(0xffffffffu, v, off);

    __shared__ double wsum[TPB / 32];
    const int lane = tid & 31;
    const int warp = tid >> 5;
    if (lane == 0) wsum[warp] = v;
    __syncthreads();

    if (tid == 0) {
        v = wsum[0] + wsum[1] + wsum[2] + wsum[3];
        atomicAdd(&g_acc, v);
        __threadfence();
        const unsigned t = atomicAdd(&g_done, 1u);
        if (t == (unsigned)nblocks - 1u) {
            const double e  = atomicAdd(&g_acc, 0.0);
            const int    bl = atomicOr(&g_blocked, 0);
            out[0] = bl ? INFINITY : (float)e;
            g_acc     = 0.0;
            g_blocked = 0;
            __threadfence();
            g_done = 0;
        }
    }
}

extern "C" void kernel_launch(void* const* d_in, const int* in_sizes, int n_in,
                              void* d_out, int out_size) {
    const float* states = (const float*)d_in[0];
    const int A = in_sizes[0] / 5;

    const int tiles   = (A + TILE - 1) / TILE;
    const int nblocks = tiles * (tiles + 1) / 2;

    nl_kernel<<<nblocks, TPB>>>(states, A, nblocks, (float*)d_out);
}

// round 9
// speedup vs baseline: 1.4150x; 1.0663x over previous
#include <cuda_runtime.h>
#include <math.h>
#include <stdint.h>

// NuclearLattice: D=3, W=64 -> box [-32,32]^3, spin in [-0.5,0.5]
// V0=10, VS=2, A_RANGE=2, KC=1.44, EPS=1e-6, PAULI_D2=1e-6.
// gauss = exp(-d2/4) = ex2(d2n) with d2n = -CSCL*d2; d2 = d2n*KINV.

#define TPB  128
#define TILE 128

#define CSCL 0.36067376f     // 0.25 * log2(e)
#define KINV (-2.7725887f)   // -1/CSCL = -4*ln(2)

__device__ double       g_acc     = 0.0;
__device__ int          g_blocked = 0;
__device__ unsigned int g_done    = 0;

typedef unsigned long long u64;

#define PK2(v, lo, hi) \
    asm("mov.b64 %0, {%1, %2};" : "=l"(v) : "f"(lo), "f"(hi))
#define UNPK2(lo, hi, v) \
    asm("mov.b64 {%0, %1}, %2;" : "=f"(lo), "=f"(hi) : "l"(v))
#define FMA2(d, a, b, c) \
    asm("fma.rn.f32x2 %0, %1, %2, %3;" : "=l"(d) : "l"(a), "l"(b), "l"(c))
#define ADD2(d, a, b) \
    asm("add.rn.f32x2 %0, %1, %2;" : "=l"(d) : "l"(a), "l"(b))
#define EX2(d, a) \
    asm("ex2.approx.f32 %0, %1;" : "=f"(d) : "f"(a))
#define RSQ(d, a) \
    asm("rsqrt.approx.f32 %0, %1;" : "=f"(d) : "f"(a))

// ---- packed fast path (off-diag, uniform tile pair): 2 j-atoms per iter ----
// smem layout (16B per j-pair, two banks 1024B apart):
//   [addr]      = {x2c_j0, x2c_j1, y2c_j0, y2c_j1}
//   [addr+1024] = {z2c_j0, z2c_j1, w_j0,   w_j1}
// where x2c = 2*CSCL*x, w = -CSCL*psq.  d2n = dot-chain + npsqi = -CSCL*d2.
template<bool COUL, bool PAULI>
__device__ __forceinline__ void fast_off_packed(
    uint32_t sbase,
    u64 xi2, u64 yi2, u64 zi2, u64 npsq2,
    float coef, float cq,
    float& accA, float& accB, float& pmaxA, float& pmaxB)
{
    u64 kinv2, eps2;
    PK2(kinv2, KINV, KINV);
    PK2(eps2, 1e-6f, 1e-6f);

    #pragma unroll 8
    for (int p = 0; p < TILE / 2; p++) {
        const uint32_t addr = sbase + p * 16;
        u64 axy0, axy1, azw0, azw1;
        asm volatile("ld.shared.v2.b64 {%0, %1}, [%2];"
                     : "=l"(axy0), "=l"(axy1) : "r"(addr));
        asm volatile("ld.shared.v2.b64 {%0, %1}, [%2+1024];"
                     : "=l"(azw0), "=l"(azw1) : "r"(addr));

        u64 t;
        FMA2(t, azw0, zi2, azw1);     // z*zi + w
        FMA2(t, axy1, yi2, t);        // + y*yi
        FMA2(t, axy0, xi2, t);        // + x*xi
        ADD2(t, t, npsq2);            // + npsqi  -> d2n pair

        float d0, d1;
        UNPK2(d0, d1, t);

        float g0, g1;
        EX2(g0, d0);
        EX2(g1, d1);
        accA = fmaf(coef, g0, accA);
        accB = fmaf(coef, g1, accB);

        if (COUL) {
            u64 v;
            FMA2(v, t, kinv2, eps2);  // max(d2,0)+eps modulo clamp below
            float v0, v1;
            UNPK2(v0, v1, v);
            v0 = fmaxf(v0, 1e-6f);
            v1 = fmaxf(v1, 1e-6f);
            float r0, r1;
            RSQ(r0, v0);
            RSQ(r1, v1);
            accA = fmaf(cq, r0, accA);
            accB = fmaf(cq, r1, accB);
        }
        if (PAULI) {
            pmaxA = fmaxf(pmaxA, d0);
            pmaxB = fmaxf(pmaxB, d1);
        }
    }
}

// ---- scalar diag fast path (uniform tile) ----
template<bool COUL>
__device__ __forceinline__ void fast_diag(
    const float4* __restrict__ sa,
    float xi, float yi, float zi, float npsqi,
    float coef, float cq, float thr, int tid, float& acc, int& pcount)
{
    #pragma unroll 8
    for (int jj = 0; jj < TILE; jj++) {
        const float4 a = sa[jj];
        float t = fmaf(a.z, zi, a.w);
        t = fmaf(a.y, yi, t);
        t = fmaf(a.x, xi, t);
        const float d2n = t + npsqi;
        float g;
        EX2(g, d2n);
        float e = coef * g;
        if (COUL) {
            const float v = fmaxf(fmaf(d2n, KINV, 1e-6f), 1e-6f);
            float r;
            RSQ(r, v);
            e = fmaf(cq, r, e);
        }
        if (jj != tid) {                        // exclude self pair
            acc += e;
            pcount += (d2n > thr) ? 1 : 0;
        }
    }
}

// ---- general fallback: exact per-pair spin/charge (any data) ----
template<bool DIAG>
__device__ __forceinline__ void gen_loop(
    const float4* __restrict__ sa,
    const float2* __restrict__ sb,              // {sp, q}
    float xi, float yi, float zi, float npsqi,
    float spi, float qi, int tid,
    float& acc, float& pmin, int& pcount)
{
    #pragma unroll 4
    for (int jj = 0; jj < TILE; jj++) {
        const float4 a = sa[jj];
        const float2 b = sb[jj];
        float t = fmaf(a.z, zi, a.w);
        t = fmaf(a.y, yi, t);
        t = fmaf(a.x, xi, t);
        const float d2n = t + npsqi;
        const float d2  = fmaxf(d2n * KINV, 0.0f);
        const float dsp = spi - b.x;
        const float dq  = qi  - b.y;
        const float d2c = fmaf(dsp, dsp, fmaf(dq, dq, d2));
        float g;
        EX2(g, d2n);
        const float coef = fmaf(2.0f * spi, b.x, -10.0f);
        float r;
        RSQ(r, d2 + 1e-6f);
        const float cq = 1.44f * qi * b.y;
        const float e  = fmaf(coef, g, cq * r);
        if (DIAG) {
            if (jj != tid) { acc += e; pcount += (d2c < 1e-6f) ? 1 : 0; }
        } else {
            acc += e; pmin = fminf(pmin, d2c);
        }
    }
}

__global__ __launch_bounds__(TPB) void nl_kernel(
    const float* __restrict__ states, int A, int nblocks, float* __restrict__ out)
{
    // Decode triangular block index k -> (bx <= by)
    const int k = blockIdx.x;
    int by = (int)((sqrtf(8.0f * (float)k + 1.0f) - 1.0f) * 0.5f);
    while ((by + 1) * (by + 2) / 2 <= k) by++;
    while (by * (by + 1) / 2 > k)       by--;
    const int bx = k - by * (by + 1) / 2;
    const bool diag = (bx == by);

    __shared__ float4 sa[TILE];          // scalar layout (diag + fallback)
    __shared__ float4 spk[2][TILE / 2];  // packed layout (off-diag fast path)
    __shared__ float2 sb[TILE];
    __shared__ float4 uref;              // {sp_i0, q_i0, sp_j0, q_j0}

    const int tid = threadIdx.x;

    // i-atom; padding far away with zero spin/charge
    const int i = bx * TILE + tid;
    const bool vi = (i < A);
    float xi = 1e18f, yi = 1e18f, zi = 1e18f, spi = 0.0f, qi = 0.0f;
    if (vi) {
        const float* s = states + (size_t)i * 5;
        xi = s[0]; yi = s[1]; zi = s[2]; spi = s[3]; qi = s[4] + 0.5f;
    }
    const float npsqi = -CSCL * fmaf(xi, xi, fmaf(yi, yi, zi * zi));

    // bounds check once per atom (each atom appears in exactly one diag block)
    if (diag && vi) {
        const bool bad = (xi  < -32.0f) || (xi  > 32.0f) ||
                         (yi  < -32.0f) || (yi  > 32.0f) ||
                         (zi  < -32.0f) || (zi  > 32.0f) ||
                         (spi < -0.5f)  || (spi > 0.5f);
        if (bad) atomicOr(&g_blocked, 1);
    }

    // j-tile -> smem (both layouts); keep j (sp,q) in regs for uniformity check
    const int j = by * TILE + tid;
    const bool vj = (j < A);
    float jsp = 0.0f, jq = 0.0f;
    {
        float x = -1e18f, y = -1e18f, z = -1e18f;
        if (vj) {
            const float* s = states + (size_t)j * 5;
            x = s[0]; y = s[1]; z = s[2]; jsp = s[3]; jq = s[4] + 0.5f;
        }
        const float psq = fmaf(x, x, fmaf(y, y, z * z));
        const float x2c = 2.0f * CSCL * x;
        const float y2c = 2.0f * CSCL * y;
        const float z2c = 2.0f * CSCL * z;
        const float w   = -CSCL * psq;
        sa[tid] = make_float4(x2c, y2c, z2c, w);
        sb[tid] = make_float2(jsp, jq);
        // packed: pair p = tid>>1, half h = tid&1
        float* P = (float*)spk;
        const int p = tid >> 1, h = tid & 1;
        P[p * 4 + h]             = x2c;
        P[p * 4 + 2 + h]         = y2c;
        P[2 * TILE + p * 4 + h]     = z2c;
        P[2 * TILE + p * 4 + 2 + h] = w;
    }
    if (tid == 0) uref = make_float4(spi, qi, jsp, jq);
    __syncthreads();

    // tile-pair uniformity: all valid atoms match the first atom of their tile
    bool myuni = (!vi || (spi == uref.x && qi == uref.y)) &&
                 (!vj || (jsp == uref.z && jq == uref.w));
    const int unified = __syncthreads_and(myuni ? 1 : 0);

    float acc    = 0.0f;
    float accB   = 0.0f;
    float pmaxA  = -1e30f, pmaxB = -1e30f;
    float pmin   = 1e30f;
    int   pcount = 0;
    bool  pauli  = false;

    if (unified) {
        const float coef = fmaf(2.0f * uref.x, uref.z, -10.0f);  // -V0 + VS*sp_i*sp_j
        const float cq   = 1.44f * uref.y * uref.w;              // KC*q_i*q_j
        const float dsp  = uref.x - uref.z;
        const float dq   = uref.y - uref.w;
        const float dcc  = fmaf(dsp, dsp, dq * dq);
        const bool  coul = (cq != 0.0f);
        const bool  pact = (dcc < 1e-6f);                        // pauli possible at all
        const float thr  = -(1e-6f - dcc) * CSCL;                // d2n > thr <=> d2+dcc < 1e-6

        if (diag) {
            if (coul) fast_diag<true >(sa, xi, yi, zi, npsqi, coef, cq, thr, tid, acc, pcount);
            else      fast_diag<false>(sa, xi, yi, zi, npsqi, coef, cq, thr, tid, acc, pcount);
            pauli = (pcount > 0);
        } else {
            const uint32_t sbase = (uint32_t)__cvta_generic_to_shared(spk);
            u64 xi2, yi2, zi2, npsq2;
            PK2(xi2, xi, xi);
            PK2(yi2, yi, yi);
            PK2(zi2, zi, zi);
            PK2(npsq2, npsqi, npsqi);
            if      ( coul &&  pact) fast_off_packed<true,  true >(sbase, xi2, yi2, zi2, npsq2, coef, cq, acc, accB, pmaxA, pmaxB);
            else if ( coul && !pact) fast_off_packed<true,  false>(sbase, xi2, yi2, zi2, npsq2, coef, cq, acc, accB, pmaxA, pmaxB);
            else if (!coul &&  pact) fast_off_packed<false, true >(sbase, xi2, yi2, zi2, npsq2, coef, cq, acc, accB, pmaxA, pmaxB);
            else                     fast_off_packed<false, false>(sbase, xi2, yi2, zi2, npsq2, coef, cq, acc, accB, pmaxA, pmaxB);
            acc += accB;
            pauli = pact && (fmaxf(pmaxA, pmaxB) > thr);
        }
    } else {
        if (diag) {
            gen_loop<true >(sa, sb, xi, yi, zi, npsqi, spi, qi, tid, acc, pmin, pcount);
            pauli = (pcount > 0);
        } else {
            gen_loop<false>(sa, sb, xi, yi, zi, npsqi, spi, qi, tid, acc, pmin, pcount);
            pauli = (pmin < 1e-6f);
        }
    }

    if (diag) acc *= 0.5f;                  // diag tiles counted both orders
    if (pauli) atomicOr(&g_blocked, 1);

    // fp32 per-thread -> double warp -> block (4 warps) -> one atomic
    double v = (double)acc;
    #pragma unroll
    for (int off = 16; off > 0; off >>= 1)
        v += __shfl_down_sync(0xffffffffu, v, off);

    __shared__ double wsum[TPB / 32];
    const int lane = tid & 31;
    const int warp = tid >> 5;
    if (lane == 0) wsum[warp] = v;
    __syncthreads();

    if (tid == 0) {
        v = wsum[0] + wsum[1] + wsum[2] + wsum[3];
        atomicAdd(&g_acc, v);
        __threadfence();
        const unsigned t = atomicAdd(&g_done, 1u);
        if (t == (unsigned)nblocks - 1u) {
            const double e  = atomicAdd(&g_acc, 0.0);
            const int    bl = atomicOr(&g_blocked, 0);
            out[0] = bl ? INFINITY : (float)e;
            g_acc     = 0.0;
            g_blocked = 0;
            __threadfence();
            g_done = 0;
        }
    }
}

extern "C" void kernel_launch(void* const* d_in, const int* in_sizes, int n_in,
                              void* d_out, int out_size) {
    const float* states = (const float*)d_in[0];
    const int A = in_sizes[0] / 5;

    const int tiles   = (A + TILE - 1) / TILE;
    const int nblocks = tiles * (tiles + 1) / 2;

    nl_kernel<<<nblocks, TPB>>>(states, A, nblocks, (float*)d_out);
}